// round 5
// baseline (speedup 1.0000x reference)
#include <cuda_runtime.h>

#define BB 8
#define TT 512
#define DD 64
#define TILE 64
#define NT (TT / TILE)               // 8 tiles per dim
#define NPAIR (NT * (NT + 1) / 2)    // 36 upper-tri tile pairs
#define TSTR 66                       // transposed [d][row] stride (floats)

// sqrt(log2(e)): pre-scale x so exp(-(dx)^2) = ex2(-(s*dx)^2)
#define SQRT_LOG2E 1.2011224087864498f

typedef unsigned long long u64;

__device__ float g_v[BB * TT * DD];   // scratch: v = x @ W^T + b (512 KB)

// ---- f32x2 packed helpers (sm_103a) --------------------------------------
__device__ __forceinline__ u64 pack2(float lo, float hi) {
    u64 r; asm("mov.b64 %0, {%1, %2};" : "=l"(r) : "f"(lo), "f"(hi)); return r;
}
__device__ __forceinline__ void unpack2(u64 v, float& lo, float& hi) {
    asm("mov.b64 {%0, %1}, %2;" : "=f"(lo), "=f"(hi) : "l"(v));
}
__device__ __forceinline__ u64 add2(u64 a, u64 b) {
    u64 r; asm("add.rn.f32x2 %0, %1, %2;" : "=l"(r) : "l"(a), "l"(b)); return r;
}
__device__ __forceinline__ u64 fma2(u64 a, u64 b, u64 c) {
    u64 r; asm("fma.rn.f32x2 %0, %1, %2, %3;" : "=l"(r) : "l"(a), "l"(b), "l"(c)); return r;
}
// e = ex2(-(a*a)): ptxas folds the negation into the FMUL source modifier
// (FMUL -R,R) -> 1 FMA-pipe op + 1 MUFU. No ALU op, shortest chain to MUFU.
__device__ __forceinline__ float exp2negsq(float a) {
    float m = -a * a;
    float r; asm("ex2.approx.ftz.f32 %0, %1;" : "=f"(r) : "f"(m));
    return r;
}

// ---------------------------------------------------------------------------
// Kernel 1: v[b,t,e] = sum_d x[b,t,d] * W[e,d] + bias[e]
// 64 blocks x 512 threads, 64 rows/block. W staged transposed once per block
// (1MB total L2 traffic). Thread = (e-group of 4, 2 rows).
// ---------------------------------------------------------------------------
#define WSTR 68
__global__ __launch_bounds__(512)
void v_kernel(const float* __restrict__ x, const float* __restrict__ W,
              const float* __restrict__ bias) {
    __shared__ float sWT[DD * WSTR];     // sWT[d*68 + e] = W[e*64 + d]
    __shared__ float sX[64 * DD];

    int tid = threadIdx.x;
    int row0 = blockIdx.x * 64;

    for (int k = tid; k < DD * DD; k += 512) {
        int e = k >> 6, d = k & 63;
        sWT[d * WSTR + e] = W[k];        // coalesced global read
    }
    for (int k = tid; k < 64 * DD; k += 512)
        sX[k] = x[row0 * DD + k];
    __syncthreads();

    int eg = tid & 15;                   // e = 4*eg .. 4*eg+3
    int rs = tid >> 4;                   // rows rs, rs+32
    float4 b4 = *(const float4*)&bias[4 * eg];
    float4 acc0 = b4, acc1 = b4;

#pragma unroll 8
    for (int d = 0; d < DD; d++) {
        float4 w4 = *(const float4*)&sWT[d * WSTR + 4 * eg];
        float x0 = sX[rs * DD + d];
        float x1 = sX[(rs + 32) * DD + d];
        acc0.x = fmaf(x0, w4.x, acc0.x);
        acc0.y = fmaf(x0, w4.y, acc0.y);
        acc0.z = fmaf(x0, w4.z, acc0.z);
        acc0.w = fmaf(x0, w4.w, acc0.w);
        acc1.x = fmaf(x1, w4.x, acc1.x);
        acc1.y = fmaf(x1, w4.y, acc1.y);
        acc1.z = fmaf(x1, w4.z, acc1.z);
        acc1.w = fmaf(x1, w4.w, acc1.w);
    }
    *(float4*)&g_v[(row0 + rs) * DD + 4 * eg]      = acc0;
    *(float4*)&g_v[(row0 + rs + 32) * DD + 4 * eg] = acc1;
}

// ---------------------------------------------------------------------------
// Kernel 2: pairwise RBF with (i,j) symmetry. Block = (b, upper-tri 64x64
// tile pair), 256 threads, 4x4 elems/thread. Inner loop: add2 (packed diff,
// j-negated at staging) -> scalar FMUL(-a,a) -> MUFU.EX2 -> packed den/ni/nj
// accumulation. Transposed [d][row] smem (stride 66): conflict-free LDS.64.
// ---------------------------------------------------------------------------
__global__ __launch_bounds__(256, 2)
void rbf_kernel(const float* __restrict__ x, float* __restrict__ out) {
    extern __shared__ float smem[];
    float* XI  = smem;                   // +s*xi   [d*66 + row]
    float* NXJ = XI  + DD * TSTR;        // -s*xj
    float* VI  = NXJ + DD * TSTR;
    float* VJ  = VI  + DD * TSTR;

    int b = blockIdx.y;
    int p = blockIdx.x;
    int ti = 0, rem = p;
    while (rem >= NT - ti) { rem -= NT - ti; ti++; }
    int tj = ti + rem;
    int i0 = ti * TILE, j0 = tj * TILE;

    int tid = threadIdx.x;
    const float* xb = x + b * TT * DD;
    const float* vb = g_v + b * TT * DD;

#pragma unroll
    for (int k = 0; k < 16; k++) {
        int idx = tid + k * 256;
        int r = idx >> 6, d = idx & 63;
        int sa = d * TSTR + r;
        XI[sa]  =  SQRT_LOG2E * xb[i0 * DD + idx];
        NXJ[sa] = -SQRT_LOG2E * xb[j0 * DD + idx];
        VI[sa]  = vb[i0 * DD + idx];
        VJ[sa]  = vb[j0 * DD + idx];
    }
    __syncthreads();

    int tx = tid & 15, ty = tid >> 4;

    u64 den[4][2], ni[4][2], nj[4][2];
#pragma unroll
    for (int r = 0; r < 4; r++)
#pragma unroll
        for (int c = 0; c < 2; c++) { den[r][c] = 0ULL; ni[r][c] = 0ULL; nj[r][c] = 0ULL; }

#pragma unroll 4
    for (int d = 0; d < DD; d++) {
        const float* XId  = XI  + d * TSTR;
        const float* VId  = VI  + d * TSTR;
        const float* NXJd = NXJ + d * TSTR;
        const float* VJd  = VJ  + d * TSTR;

        float2 fiA = *(const float2*)&XId[2 * ty];        // broadcast
        float2 fiB = *(const float2*)&XId[2 * ty + 32];
        float2 fvA = *(const float2*)&VId[2 * ty];
        float2 fvB = *(const float2*)&VId[2 * ty + 32];
        u64 njc[2], jvc[2];
        njc[0] = *(const u64*)&NXJd[2 * tx];              // spread, conflict-free
        njc[1] = *(const u64*)&NXJd[2 * tx + 32];
        jvc[0] = *(const u64*)&VJd[2 * tx];
        jvc[1] = *(const u64*)&VJd[2 * tx + 32];

        float fi[4] = {fiA.x, fiA.y, fiB.x, fiB.y};
        float fv[4] = {fvA.x, fvA.y, fvB.x, fvB.y};

#pragma unroll
        for (int r = 0; r < 4; r++) {
            u64 fid = pack2(fi[r], fi[r]);
            u64 fvd = pack2(fv[r], fv[r]);
#pragma unroll
            for (int c = 0; c < 2; c++) {
                u64 a2 = add2(fid, njc[c]);      // s*(xi - xj), 2 elems
                float a0, a1; unpack2(a2, a0, a1);     // reg-pair, ~free
                float e0 = exp2negsq(a0);        // FMUL(-a,a) + MUFU.EX2
                float e1 = exp2negsq(a1);
                u64 e2 = pack2(e0, e1);
                den[r][c] = add2(den[r][c], e2);
                ni[r][c]  = fma2(e2, fvd, ni[r][c]);
                nj[r][c]  = fma2(e2, jvc[c], nj[r][c]);
            }
        }
    }

    float* ob = out + (size_t)b * TT * TT;
    int rowOf[4] = {2 * ty, 2 * ty + 1, 2 * ty + 32, 2 * ty + 33};

    float oi[4][2][2], oj[4][2][2];
#pragma unroll
    for (int r = 0; r < 4; r++)
#pragma unroll
        for (int c = 0; c < 2; c++) {
            float d0, d1, n0, n1, q0, q1;
            unpack2(den[r][c], d0, d1);
            unpack2(ni[r][c],  n0, n1);
            unpack2(nj[r][c],  q0, q1);
            float rc0, rc1;
            asm("rcp.approx.ftz.f32 %0, %1;" : "=f"(rc0) : "f"(d0));
            asm("rcp.approx.ftz.f32 %0, %1;" : "=f"(rc1) : "f"(d1));
            oi[r][c][0] = n0 * rc0; oi[r][c][1] = n1 * rc1;
            oj[r][c][0] = q0 * rc0; oj[r][c][1] = q1 * rc1;
        }

    // main writes: float2, coalesced across tx
#pragma unroll
    for (int r = 0; r < 4; r++) {
        int gi = i0 + rowOf[r];
#pragma unroll
        for (int c = 0; c < 2; c++) {
            float2 w = make_float2(oi[r][c][0], oi[r][c][1]);
            *(float2*)&ob[(size_t)gi * TT + j0 + 2 * tx + 32 * c] = w;
        }
    }

    if (ti != tj) {
        // mirror: out[b, gj, gi..gi+1]
#pragma unroll
        for (int c = 0; c < 2; c++) {
#pragma unroll
            for (int e = 0; e < 2; e++) {
                int gj = j0 + 2 * tx + 32 * c + e;
                float2 w0 = make_float2(oj[0][c][e], oj[1][c][e]);
                float2 w1 = make_float2(oj[2][c][e], oj[3][c][e]);
                *(float2*)&ob[(size_t)gj * TT + i0 + 2 * ty]      = w0;
                *(float2*)&ob[(size_t)gj * TT + i0 + 2 * ty + 32] = w1;
            }
        }
    }
}

extern "C" void kernel_launch(void* const* d_in, const int* in_sizes, int n_in,
                              void* d_out, int out_size) {
    const float* x = (const float*)d_in[0];    // (8,512,64)
    const float* W = (const float*)d_in[1];    // (64,64)
    const float* bias = (const float*)d_in[2]; // (64,)
    float* out = (float*)d_out;                // (8,512,512)

    static bool attr_set = false;
    size_t smem_bytes = 4 * DD * TSTR * sizeof(float);   // 67584
    if (!attr_set) {
        cudaFuncSetAttribute(rbf_kernel,
                             cudaFuncAttributeMaxDynamicSharedMemorySize,
                             (int)smem_bytes);
        attr_set = true;
    }

    v_kernel<<<(BB * TT) / 64, 512>>>(x, W, bias);
    rbf_kernel<<<dim3(NPAIR, BB), 256, smem_bytes>>>(x, out);
}